// round 1
// baseline (speedup 1.0000x reference)
#include <cuda_runtime.h>

#define N_IMGS 2
#define C_CH   256
#define HW_DIM 64
#define HWPIX  (HW_DIM * HW_DIM)      // 4096
#define NPIX   (N_IMGS * HWPIX)       // 8192
#define S_STEPS 64
#define EPSV 1e-3f

// ---------------- scratch (device globals: no allocation allowed) ----------
__device__ float  g_F[N_IMGS][9];
__device__ float  g_feat2T[N_IMGS * HWPIX * C_CH];       // (N, H*W, C)  8 MB
__device__ float4 g_w[NPIX * S_STEPS];                   // masked bilinear weights, 8 MB
__device__ int4   g_off[NPIX * S_STEPS];                 // float4-indices of 4 corners, 8 MB

// ---------------- F computation (fp64, closed form) -------------------------
__device__ __forceinline__ double det3c(const double a[3], const double b[3], const double c[3]) {
    return a[0]*(b[1]*c[2]-b[2]*c[1])
         - a[1]*(b[0]*c[2]-b[2]*c[0])
         + a[2]*(b[0]*c[1]-b[1]*c[0]);
}

__global__ void compute_F_kernel(const float* __restrict__ P1g, const float* __restrict__ P2g) {
    int n = threadIdx.x;
    if (n >= N_IMGS) return;
    double p1[3][4], p2[3][4];
    for (int i = 0; i < 3; i++)
        for (int j = 0; j < 4; j++) {
            p1[i][j] = (double)P1g[n*12 + i*4 + j];
            p2[i][j] = (double)P2g[n*12 + i*4 + j];
        }
    // columns of P1
    double col[4][3];
    for (int j = 0; j < 4; j++)
        for (int i = 0; i < 3; i++) col[j][i] = p1[i][j];
    // null vector of P1 (camera center, homogeneous) via 4D cofactors
    double v[4];
    v[0] =  det3c(col[1], col[2], col[3]);
    v[1] = -det3c(col[0], col[2], col[3]);
    v[2] =  det3c(col[0], col[1], col[3]);
    v[3] = -det3c(col[0], col[1], col[2]);
    double nrm = sqrt(v[0]*v[0] + v[1]*v[1] + v[2]*v[2] + v[3]*v[3]);
    for (int j = 0; j < 4; j++) v[j] /= nrm;   // match eigh's unit-norm convention
    // epipole in image 2
    double e2[3];
    for (int i = 0; i < 3; i++)
        e2[i] = p2[i][0]*v[0] + p2[i][1]*v[1] + p2[i][2]*v[2] + p2[i][3]*v[3];
    // G = P1 P1^T (3x3), then Ginv
    double G[3][3];
    for (int i = 0; i < 3; i++)
        for (int k = 0; k < 3; k++) {
            double s = 0.0;
            for (int j = 0; j < 4; j++) s += p1[i][j]*p1[k][j];
            G[i][k] = s;
        }
    double detG = G[0][0]*(G[1][1]*G[2][2]-G[1][2]*G[2][1])
                - G[0][1]*(G[1][0]*G[2][2]-G[1][2]*G[2][0])
                + G[0][2]*(G[1][0]*G[2][1]-G[1][1]*G[2][0]);
    double Gi[3][3];
    Gi[0][0] =  (G[1][1]*G[2][2]-G[1][2]*G[2][1])/detG;
    Gi[0][1] = -(G[0][1]*G[2][2]-G[0][2]*G[2][1])/detG;
    Gi[0][2] =  (G[0][1]*G[1][2]-G[0][2]*G[1][1])/detG;
    Gi[1][0] = -(G[1][0]*G[2][2]-G[1][2]*G[2][0])/detG;
    Gi[1][1] =  (G[0][0]*G[2][2]-G[0][2]*G[2][0])/detG;
    Gi[1][2] = -(G[0][0]*G[1][2]-G[0][2]*G[1][0])/detG;
    Gi[2][0] =  (G[1][0]*G[2][1]-G[1][1]*G[2][0])/detG;
    Gi[2][1] = -(G[0][0]*G[2][1]-G[0][1]*G[2][0])/detG;
    Gi[2][2] =  (G[0][0]*G[1][1]-G[0][1]*G[1][0])/detG;
    // pinv(P1) = P1^T Ginv  (4x3)
    double pinv[4][3];
    for (int m = 0; m < 4; m++)
        for (int j = 0; j < 3; j++) {
            double s = 0.0;
            for (int k = 0; k < 3; k++) s += p1[k][m]*Gi[k][j];
            pinv[m][j] = s;
        }
    // B = P2 @ pinv (3x3)
    double B[3][3];
    for (int i = 0; i < 3; i++)
        for (int j = 0; j < 3; j++) {
            double s = 0.0;
            for (int m = 0; m < 4; m++) s += p2[i][m]*pinv[m][j];
            B[i][j] = s;
        }
    // F = skew(e2) @ B
    double F[3][3];
    for (int j = 0; j < 3; j++) {
        F[0][j] = -e2[2]*B[1][j] + e2[1]*B[2][j];
        F[1][j] =  e2[2]*B[0][j] - e2[0]*B[2][j];
        F[2][j] = -e2[1]*B[0][j] + e2[0]*B[1][j];
    }
    for (int i = 0; i < 3; i++)
        for (int j = 0; j < 3; j++)
            g_F[n][i*3+j] = (float)F[i][j];
}

// ---------------- transpose feat2 (N,C,HW) -> (N,HW,C) ----------------------
__global__ void transpose_kernel(const float* __restrict__ in) {
    __shared__ float tile[32][33];
    int n  = blockIdx.z;
    int pt = blockIdx.x * 32;   // pixel tile
    int ct = blockIdx.y * 32;   // channel tile
    int tx = threadIdx.x, ty = threadIdx.y;   // (32, 8)
    const float* src = in + (size_t)n * C_CH * HWPIX;
    #pragma unroll
    for (int k = 0; k < 4; k++)
        tile[ty + 8*k][tx] = src[(ct + ty + 8*k) * HWPIX + pt + tx];
    __syncthreads();
    float* dst = g_feat2T + (size_t)n * HWPIX * C_CH;
    #pragma unroll
    for (int k = 0; k < 4; k++)
        dst[(pt + ty + 8*k) * C_CH + ct + tx] = tile[tx][ty + 8*k];
}

// ---------------- per-(pixel,s) sample locations -> weights/offsets ---------
__global__ __launch_bounds__(256) void locs_kernel() {
    int s  = threadIdx.x;                      // 0..63
    int gp = blockIdx.x * 4 + threadIdx.y;     // global pixel id
    int n  = gp >> 12;
    int p  = gp & 4095;
    float hf = (float)(p >> 6);
    float wf = (float)(p & 63);
    const float* F = g_F[n];
    float a = F[0]*wf + F[1]*hf + F[2];
    float b = F[3]*wf + F[4]*hf + F[5];
    float c = F[6]*wf + F[7]*hf + F[8];
    float sb = (b > 0.f) ? 1.f : ((b < 0.f) ? -1.f : 0.f);
    float sa = (a > 0.f) ? 1.f : ((a < 0.f) ? -1.f : 0.f);
    float db = sb * fmaxf(fabsf(b), EPSV);
    float da = sa * fmaxf(fabsf(a), EPSV);
    const float xmax = 63.f, ymax = 63.f;
    float by1 = -c / db;
    float by2 = -(xmax*a + c) / db;
    float bx0 = -c / da;
    float bx3 = -(ymax*b + c) / da;
    float px[4] = {bx0, 0.f, xmax, bx3};
    float py[4] = {0.f, by1, by2, ymax};
    bool m0 = (bx0 >= EPSV) && (bx0 <  xmax - EPSV);
    bool m1 = (by1 >  EPSV) && (by1 <= ymax - EPSV);
    bool m2 = (by2 >= EPSV) && (by2 <  ymax - EPSV);
    bool m3 = (bx3 >  EPSV) && (bx3 <= xmax - EPSV);
    int nint = (int)m0 + (int)m1 + (int)m2 + (int)m3;
    bool valid2 = nint >= 2;
    bool mm[4];
    if (valid2) { mm[0]=m0; mm[1]=m1; mm[2]=m2; mm[3]=m3; }
    else        { mm[0]=true; mm[1]=true; mm[2]=false; mm[3]=false; }
    int i0 = -1, i1 = -1;
    #pragma unroll
    for (int i = 0; i < 4; i++) {
        if (mm[i]) { if (i0 < 0) i0 = i; else if (i1 < 0) i1 = i; }
    }
    float sx, sy, vx, vy;
    if (valid2) { sx = px[i0]; sy = py[i0]; vx = px[i1]-px[i0]; vy = py[i1]-py[i0]; }
    else        { sx = -10000.f; sy = -10000.f; vx = 0.f; vy = 0.f; }

    float t  = (float)s / 63.0f;
    float lx = sx + vx * t;
    float ly = sy + vy * t;
    float gx = lx / 63.0f * 2.0f - 1.0f;
    float gy = ly / 63.0f * 2.0f - 1.0f;
    float x  = (gx + 1.0f) * 32.0f - 0.5f;
    float y  = (gy + 1.0f) * 32.0f - 0.5f;
    float x0 = floorf(x), y0 = floorf(y);
    float wx1 = x - x0, wy1 = y - y0;
    bool vx0 = (x0        >= 0.f) && (x0        < 64.f);
    bool vx1 = (x0 + 1.f  >= 0.f) && (x0 + 1.f  < 64.f);
    bool vy0 = (y0        >= 0.f) && (y0        < 64.f);
    bool vy1 = (y0 + 1.f  >= 0.f) && (y0 + 1.f  < 64.f);
    float4 w;
    w.x = (vx0 && vy0) ? (1.f - wx1) * (1.f - wy1) : 0.f;
    w.y = (vx1 && vy0) ? wx1 * (1.f - wy1)         : 0.f;
    w.z = (vx0 && vy1) ? (1.f - wx1) * wy1         : 0.f;
    w.w = (vx1 && vy1) ? wx1 * wy1                 : 0.f;
    int cx0 = (int)fminf(fmaxf(x0,       0.f), 63.f);
    int cx1 = (int)fminf(fmaxf(x0 + 1.f, 0.f), 63.f);
    int cy0 = (int)fminf(fmaxf(y0,       0.f), 63.f);
    int cy1 = (int)fminf(fmaxf(y0 + 1.f, 0.f), 63.f);
    int nb = n * HWPIX;
    int4 o;
    o.x = (nb + cy0*64 + cx0) * (C_CH/4);
    o.y = (nb + cy0*64 + cx1) * (C_CH/4);
    o.z = (nb + cy1*64 + cx0) * (C_CH/4);
    o.w = (nb + cy1*64 + cx1) * (C_CH/4);
    g_w  [gp*S_STEPS + s] = w;
    g_off[gp*S_STEPS + s] = o;
}

// ---------------- main sampling + max-over-S kernel --------------------------
__global__ __launch_bounds__(256) void sample_kernel(float* __restrict__ out) {
    __shared__ float4 sw[4][S_STEPS];
    __shared__ int4   so[4][S_STEPS];
    int x  = threadIdx.x;                    // 0..63  -> channel group (4 ch)
    int y  = threadIdx.y;                    // 0..3   -> pixel in block
    int gp = blockIdx.x * 4 + y;
    sw[y][x] = g_w  [gp*S_STEPS + x];
    so[y][x] = g_off[gp*S_STEPS + x];
    __syncthreads();
    const float4* f = (const float4*)g_feat2T;
    float4 acc = make_float4(-3.4e38f, -3.4e38f, -3.4e38f, -3.4e38f);
    #pragma unroll 4
    for (int s = 0; s < S_STEPS; s++) {
        float4 w = sw[y][s];
        int4   o = so[y][s];
        if (w.x == 0.f && w.y == 0.f && w.z == 0.f && w.w == 0.f) {
            // zero-weight sample contributes exactly 0 to the max
            acc.x = fmaxf(acc.x, 0.f);
            acc.y = fmaxf(acc.y, 0.f);
            acc.z = fmaxf(acc.z, 0.f);
            acc.w = fmaxf(acc.w, 0.f);
            continue;
        }
        float4 v0 = f[o.x + x];
        float4 v1 = f[o.y + x];
        float4 v2 = f[o.z + x];
        float4 v3 = f[o.w + x];
        float r;
        r = fmaf(w.x, v0.x, fmaf(w.y, v1.x, fmaf(w.z, v2.x, w.w * v3.x))); acc.x = fmaxf(acc.x, r);
        r = fmaf(w.x, v0.y, fmaf(w.y, v1.y, fmaf(w.z, v2.y, w.w * v3.y))); acc.y = fmaxf(acc.y, r);
        r = fmaf(w.x, v0.z, fmaf(w.y, v1.z, fmaf(w.z, v2.z, w.w * v3.z))); acc.z = fmaxf(acc.z, r);
        r = fmaf(w.x, v0.w, fmaf(w.y, v1.w, fmaf(w.z, v2.w, w.w * v3.w))); acc.w = fmaxf(acc.w, r);
    }
    int n = gp >> 12;
    int p = gp & 4095;
    int cbase = x * 4;
    float* op = out + ((size_t)(n * C_CH + cbase)) * HWPIX + p;
    op[0*HWPIX] = acc.x;
    op[1*HWPIX] = acc.y;
    op[2*HWPIX] = acc.z;
    op[3*HWPIX] = acc.w;
}

// ---------------- launch ------------------------------------------------------
extern "C" void kernel_launch(void* const* d_in, const int* in_sizes, int n_in,
                              void* d_out, int out_size) {
    (void)in_sizes; (void)n_in; (void)out_size;
    const float* feat2 = (const float*)d_in[1];
    const float* P1    = (const float*)d_in[2];
    const float* P2    = (const float*)d_in[3];

    compute_F_kernel<<<1, 32>>>(P1, P2);

    dim3 tb(32, 8);
    dim3 tg(HWPIX / 32, C_CH / 32, N_IMGS);
    transpose_kernel<<<tg, tb>>>(feat2);

    locs_kernel<<<NPIX / 4, dim3(64, 4)>>>();

    sample_kernel<<<NPIX / 4, dim3(64, 4)>>>((float*)d_out);
}

// round 3
// speedup vs baseline: 1.6700x; 1.6700x over previous
#include <cuda_runtime.h>
#include <cuda_fp16.h>

#define N_IMGS 2
#define C_CH   256
#define HW_DIM 64
#define HWPIX  (HW_DIM * HW_DIM)      // 4096
#define NPIX   (N_IMGS * HWPIX)       // 8192
#define S_STEPS 64
#define EPSV 1e-3f

// ---------------- scratch (device globals: no allocation allowed) ----------
__device__ float g_F[N_IMGS][9];
// feat2 transposed to (N, H*W, C) in half precision; uint4-aligned (8 halves per uint4)
__device__ uint4 g_feat2h[(size_t)N_IMGS * HWPIX * C_CH / 8];   // 4 MB

// ---------------- F computation (fp64, closed form) -------------------------
__device__ __forceinline__ double det3c(const double a[3], const double b[3], const double c[3]) {
    return a[0]*(b[1]*c[2]-b[2]*c[1])
         - a[1]*(b[0]*c[2]-b[2]*c[0])
         + a[2]*(b[0]*c[1]-b[1]*c[0]);
}

__global__ void compute_F_kernel(const float* __restrict__ P1g, const float* __restrict__ P2g) {
    int n = threadIdx.x;
    if (n >= N_IMGS) return;
    double p1[3][4], p2[3][4];
    for (int i = 0; i < 3; i++)
        for (int j = 0; j < 4; j++) {
            p1[i][j] = (double)P1g[n*12 + i*4 + j];
            p2[i][j] = (double)P2g[n*12 + i*4 + j];
        }
    double col[4][3];
    for (int j = 0; j < 4; j++)
        for (int i = 0; i < 3; i++) col[j][i] = p1[i][j];
    double v[4];
    v[0] =  det3c(col[1], col[2], col[3]);
    v[1] = -det3c(col[0], col[2], col[3]);
    v[2] =  det3c(col[0], col[1], col[3]);
    v[3] = -det3c(col[0], col[1], col[2]);
    double nrm = sqrt(v[0]*v[0] + v[1]*v[1] + v[2]*v[2] + v[3]*v[3]);
    for (int j = 0; j < 4; j++) v[j] /= nrm;
    double e2[3];
    for (int i = 0; i < 3; i++)
        e2[i] = p2[i][0]*v[0] + p2[i][1]*v[1] + p2[i][2]*v[2] + p2[i][3]*v[3];
    double G[3][3];
    for (int i = 0; i < 3; i++)
        for (int k = 0; k < 3; k++) {
            double s = 0.0;
            for (int j = 0; j < 4; j++) s += p1[i][j]*p1[k][j];
            G[i][k] = s;
        }
    double detG = G[0][0]*(G[1][1]*G[2][2]-G[1][2]*G[2][1])
                - G[0][1]*(G[1][0]*G[2][2]-G[1][2]*G[2][0])
                + G[0][2]*(G[1][0]*G[2][1]-G[1][1]*G[2][0]);
    double Gi[3][3];
    Gi[0][0] =  (G[1][1]*G[2][2]-G[1][2]*G[2][1])/detG;
    Gi[0][1] = -(G[0][1]*G[2][2]-G[0][2]*G[2][1])/detG;
    Gi[0][2] =  (G[0][1]*G[1][2]-G[0][2]*G[1][1])/detG;
    Gi[1][0] = -(G[1][0]*G[2][2]-G[1][2]*G[2][0])/detG;
    Gi[1][1] =  (G[0][0]*G[2][2]-G[0][2]*G[2][0])/detG;
    Gi[1][2] = -(G[0][0]*G[1][2]-G[0][2]*G[1][0])/detG;
    Gi[2][0] =  (G[1][0]*G[2][1]-G[1][1]*G[2][0])/detG;
    Gi[2][1] = -(G[0][0]*G[2][1]-G[0][1]*G[2][0])/detG;
    Gi[2][2] =  (G[0][0]*G[1][1]-G[0][1]*G[1][0])/detG;
    double pinv[4][3];
    for (int m = 0; m < 4; m++)
        for (int j = 0; j < 3; j++) {
            double s = 0.0;
            for (int k = 0; k < 3; k++) s += p1[k][m]*Gi[k][j];
            pinv[m][j] = s;
        }
    double B[3][3];
    for (int i = 0; i < 3; i++)
        for (int j = 0; j < 3; j++) {
            double s = 0.0;
            for (int m = 0; m < 4; m++) s += p2[i][m]*pinv[m][j];
            B[i][j] = s;
        }
    double F[3][3];
    for (int j = 0; j < 3; j++) {
        F[0][j] = -e2[2]*B[1][j] + e2[1]*B[2][j];
        F[1][j] =  e2[2]*B[0][j] - e2[0]*B[2][j];
        F[2][j] = -e2[1]*B[0][j] + e2[0]*B[1][j];
    }
    for (int i = 0; i < 3; i++)
        for (int j = 0; j < 3; j++)
            g_F[n][i*3+j] = (float)F[i][j];
}

// ---------------- transpose+convert feat2 (N,C,HW) fp32 -> (N,HW,C) half ----
__global__ void transpose_kernel(const float* __restrict__ in) {
    __shared__ float tile[32][33];      // tile[channel-within-32][pixel-within-32]
    int n  = blockIdx.z;
    int pt = blockIdx.x * 32;   // pixel tile
    int ct = blockIdx.y * 32;   // channel tile
    int tx = threadIdx.x, ty = threadIdx.y;   // (32, 8)
    const float* src = in + (size_t)n * C_CH * HWPIX;
    #pragma unroll
    for (int k = 0; k < 4; k++)
        tile[ty + 8*k][tx] = src[(ct + ty + 8*k) * HWPIX + pt + tx];
    __syncthreads();
    __half* dst = (__half*)g_feat2h + (size_t)n * HWPIX * C_CH;
    int tid = ty * 32 + tx;
    int c2  = tid & 15;         // half2 index within 32 channels
    int pr  = tid >> 4;         // 0..15 pixel row
    #pragma unroll
    for (int k = 0; k < 2; k++) {
        int row = pr + 16*k;    // pixel within tile
        // FIX: tile is [channel][pixel]; channel = 2*c2(+1), pixel = row
        __half2 v = __floats2half2_rn(tile[2*c2][row], tile[2*c2+1][row]);
        ((__half2*)(dst + (size_t)(pt + row) * C_CH + ct))[c2] = v;
    }
}

// ---------------- fused locs + sampling + max-over-S kernel -----------------
// 1 warp = 1 pixel (all 256 channels), 8 warps/block.
__global__ __launch_bounds__(256) void sample_kernel(float* __restrict__ out) {
    __shared__ uint4 s_wgt[8][S_STEPS];   // 4 packed half2 weights per sample (8KB)
    __shared__ int4  s_off[8][S_STEPS];   // 4 corner uint4-indices (base)    (8KB)
    int lane = threadIdx.x;               // 0..31
    int wy   = threadIdx.y;               // 0..7 pixel-in-block
    int gp   = blockIdx.x * 8 + wy;
    int n    = gp >> 12;
    int p    = gp & 4095;

    // ---- phase A: epipolar line + per-sample weights/offsets (fp32) ----
    {
        float hf = (float)(p >> 6);
        float wf = (float)(p & 63);
        const float* F = g_F[n];
        float a = F[0]*wf + F[1]*hf + F[2];
        float b = F[3]*wf + F[4]*hf + F[5];
        float c = F[6]*wf + F[7]*hf + F[8];
        float sb = (b > 0.f) ? 1.f : ((b < 0.f) ? -1.f : 0.f);
        float sa = (a > 0.f) ? 1.f : ((a < 0.f) ? -1.f : 0.f);
        float db = sb * fmaxf(fabsf(b), EPSV);
        float da = sa * fmaxf(fabsf(a), EPSV);
        const float xmax = 63.f, ymax = 63.f;
        float by1 = -c / db;
        float by2 = -(xmax*a + c) / db;
        float bx0 = -c / da;
        float bx3 = -(ymax*b + c) / da;
        float px[4] = {bx0, 0.f, xmax, bx3};
        float py[4] = {0.f, by1, by2, ymax};
        bool m0 = (bx0 >= EPSV) && (bx0 <  xmax - EPSV);
        bool m1 = (by1 >  EPSV) && (by1 <= ymax - EPSV);
        bool m2 = (by2 >= EPSV) && (by2 <  ymax - EPSV);
        bool m3 = (bx3 >  EPSV) && (bx3 <= xmax - EPSV);
        int nint = (int)m0 + (int)m1 + (int)m2 + (int)m3;
        bool valid2 = nint >= 2;
        bool mm[4];
        if (valid2) { mm[0]=m0; mm[1]=m1; mm[2]=m2; mm[3]=m3; }
        else        { mm[0]=true; mm[1]=true; mm[2]=false; mm[3]=false; }
        int i0 = -1, i1 = -1;
        #pragma unroll
        for (int i = 0; i < 4; i++) {
            if (mm[i]) { if (i0 < 0) i0 = i; else if (i1 < 0) i1 = i; }
        }
        float sx, sy, vx, vy;
        if (valid2) { sx = px[i0]; sy = py[i0]; vx = px[i1]-px[i0]; vy = py[i1]-py[i0]; }
        else        { sx = -10000.f; sy = -10000.f; vx = 0.f; vy = 0.f; }

        int nb = n * HWPIX;
        #pragma unroll
        for (int t2 = 0; t2 < 2; t2++) {
            int s = lane + 32*t2;
            float t  = (float)s / 63.0f;
            float lx = sx + vx * t;
            float ly = sy + vy * t;
            float gx = lx / 63.0f * 2.0f - 1.0f;
            float gy = ly / 63.0f * 2.0f - 1.0f;
            float x  = (gx + 1.0f) * 32.0f - 0.5f;
            float y  = (gy + 1.0f) * 32.0f - 0.5f;
            float x0 = floorf(x), y0 = floorf(y);
            float wx1 = x - x0, wy1 = y - y0;
            bool vx0 = (x0        >= 0.f) && (x0        < 64.f);
            bool vx1 = (x0 + 1.f  >= 0.f) && (x0 + 1.f  < 64.f);
            bool vy0 = (y0        >= 0.f) && (y0        < 64.f);
            bool vy1 = (y0 + 1.f  >= 0.f) && (y0 + 1.f  < 64.f);
            float w0 = (vx0 && vy0) ? (1.f - wx1) * (1.f - wy1) : 0.f;
            float w1 = (vx1 && vy0) ? wx1 * (1.f - wy1)         : 0.f;
            float w2 = (vx0 && vy1) ? (1.f - wx1) * wy1         : 0.f;
            float w3 = (vx1 && vy1) ? wx1 * wy1                 : 0.f;
            // pack each weight as half2 (dup)
            unsigned u0 = (unsigned)__half_as_ushort(__float2half_rn(w0)) * 0x10001u;
            unsigned u1 = (unsigned)__half_as_ushort(__float2half_rn(w1)) * 0x10001u;
            unsigned u2 = (unsigned)__half_as_ushort(__float2half_rn(w2)) * 0x10001u;
            unsigned u3 = (unsigned)__half_as_ushort(__float2half_rn(w3)) * 0x10001u;
            int cx0 = (int)fminf(fmaxf(x0,       0.f), 63.f);
            int cx1 = (int)fminf(fmaxf(x0 + 1.f, 0.f), 63.f);
            int cy0 = (int)fminf(fmaxf(y0,       0.f), 63.f);
            int cy1 = (int)fminf(fmaxf(y0 + 1.f, 0.f), 63.f);
            int4 o;
            o.x = (nb + cy0*64 + cx0) * (C_CH/8);
            o.y = (nb + cy0*64 + cx1) * (C_CH/8);
            o.z = (nb + cy1*64 + cx0) * (C_CH/8);
            o.w = (nb + cy1*64 + cx1) * (C_CH/8);
            s_wgt[wy][s] = make_uint4(u0, u1, u2, u3);
            s_off[wy][s] = o;
        }
    }
    __syncwarp();

    // ---- phase B: sample loop, half2 interp + max ----
    const __half2 h2zero = __float2half2_rn(0.0f);
    __half2 a0 = __float2half2_rn(-65504.f);
    __half2 a1 = a0, a2 = a0, a3 = a0;
    const uint4* f = (const uint4*)g_feat2h;
    #pragma unroll 2
    for (int s = 0; s < S_STEPS; s++) {
        uint4 wp = s_wgt[wy][s];
        if ((wp.x | wp.y | wp.z | wp.w) == 0u) {
            a0 = __hmax2(a0, h2zero);
            a1 = __hmax2(a1, h2zero);
            a2 = __hmax2(a2, h2zero);
            a3 = __hmax2(a3, h2zero);
            continue;
        }
        int4 o = s_off[wy][s];
        uint4 r0 = f[o.x + lane];
        uint4 r1 = f[o.y + lane];
        uint4 r2 = f[o.z + lane];
        uint4 r3 = f[o.w + lane];
        __half2 w0 = *reinterpret_cast<__half2*>(&wp.x);
        __half2 w1 = *reinterpret_cast<__half2*>(&wp.y);
        __half2 w2 = *reinterpret_cast<__half2*>(&wp.z);
        __half2 w3 = *reinterpret_cast<__half2*>(&wp.w);
        const __half2* h0 = reinterpret_cast<const __half2*>(&r0);
        const __half2* h1 = reinterpret_cast<const __half2*>(&r1);
        const __half2* h2 = reinterpret_cast<const __half2*>(&r2);
        const __half2* h3 = reinterpret_cast<const __half2*>(&r3);
        __half2 v;
        v = __hmul2(w3, h3[0]); v = __hfma2(w2, h2[0], v); v = __hfma2(w1, h1[0], v); v = __hfma2(w0, h0[0], v);
        a0 = __hmax2(a0, v);
        v = __hmul2(w3, h3[1]); v = __hfma2(w2, h2[1], v); v = __hfma2(w1, h1[1], v); v = __hfma2(w0, h0[1], v);
        a1 = __hmax2(a1, v);
        v = __hmul2(w3, h3[2]); v = __hfma2(w2, h2[2], v); v = __hfma2(w1, h1[2], v); v = __hfma2(w0, h0[2], v);
        a2 = __hmax2(a2, v);
        v = __hmul2(w3, h3[3]); v = __hfma2(w2, h2[3], v); v = __hfma2(w1, h1[3], v); v = __hfma2(w0, h0[3], v);
        a3 = __hmax2(a3, v);
    }

    // ---- stage results into shared (reuse this warp's s_wgt row: 256 floats) ----
    {
        float* sOutW = (float*)&s_wgt[wy][0];
        float2 t;
        t = __half22float2(a0); sOutW[lane*8 + 0] = t.x; sOutW[lane*8 + 1] = t.y;
        t = __half22float2(a1); sOutW[lane*8 + 2] = t.x; sOutW[lane*8 + 3] = t.y;
        t = __half22float2(a2); sOutW[lane*8 + 4] = t.x; sOutW[lane*8 + 5] = t.y;
        t = __half22float2(a3); sOutW[lane*8 + 6] = t.x; sOutW[lane*8 + 7] = t.y;
    }
    __syncthreads();

    // ---- coalesced store: thread = channel, 8 pixels -> 2x STG.128 ----
    {
        int c   = wy * 32 + lane;          // 0..255
        const float* sOut = (const float*)&s_wgt[0][0];   // [pix*256 + c]
        int gpb = blockIdx.x * 8;
        int nB  = gpb >> 12;
        int pB  = gpb & 4095;
        float4 o1 = make_float4(sOut[0*256 + c], sOut[1*256 + c],
                                sOut[2*256 + c], sOut[3*256 + c]);
        float4 o2 = make_float4(sOut[4*256 + c], sOut[5*256 + c],
                                sOut[6*256 + c], sOut[7*256 + c]);
        size_t base = ((size_t)(nB * C_CH + c)) * HWPIX + pB;
        *reinterpret_cast<float4*>(out + base)     = o1;
        *reinterpret_cast<float4*>(out + base + 4) = o2;
    }
}

// ---------------- launch ------------------------------------------------------
extern "C" void kernel_launch(void* const* d_in, const int* in_sizes, int n_in,
                              void* d_out, int out_size) {
    (void)in_sizes; (void)n_in; (void)out_size;
    const float* feat2 = (const float*)d_in[1];
    const float* P1    = (const float*)d_in[2];
    const float* P2    = (const float*)d_in[3];

    compute_F_kernel<<<1, 32>>>(P1, P2);

    dim3 tb(32, 8);
    dim3 tg(HWPIX / 32, C_CH / 32, N_IMGS);
    transpose_kernel<<<tg, tb>>>(feat2);

    sample_kernel<<<NPIX / 8, dim3(32, 8)>>>((float*)d_out);
}

// round 4
// speedup vs baseline: 1.9358x; 1.1592x over previous
#include <cuda_runtime.h>
#include <cuda_fp16.h>

#define N_IMGS 2
#define C_CH   256
#define HW_DIM 64
#define HWPIX  (HW_DIM * HW_DIM)      // 4096
#define NPIX   (N_IMGS * HWPIX)       // 8192
#define S_STEPS 64
#define EPSV 1e-3f

// ---------------- scratch (device globals: no allocation allowed) ----------
__device__ float g_F[N_IMGS][9];
// feat2 transposed to (N, H*W, C) in half precision; uint4-aligned (8 halves per uint4)
__device__ uint4 g_feat2h[(size_t)N_IMGS * HWPIX * C_CH / 8];   // 4 MB

__device__ __forceinline__ double det3cols(const double c0[3], const double c1[3], const double c2[3]) {
    return c0[0]*(c1[1]*c2[2]-c1[2]*c2[1])
         - c0[1]*(c1[0]*c2[2]-c1[2]*c2[0])
         + c0[2]*(c1[0]*c2[1]-c1[1]*c2[0]);
}

// ---------------- fused prep: block 0 computes F (warp-parallel fp64),
// ---------------- blocks 1..2048 transpose+convert feat2 to (N,HW,C) half --
__global__ __launch_bounds__(256) void prep_kernel(const float* __restrict__ feat2,
                                                   const float* __restrict__ P1g,
                                                   const float* __restrict__ P2g) {
    __shared__ float tile[32][33];            // transpose staging
    __shared__ double s_v[N_IMGS][4];
    __shared__ double s_e2[N_IMGS][3];
    __shared__ double s_G[N_IMGS][9];
    __shared__ double s_Gi[N_IMGS][9];
    __shared__ double s_pinv[N_IMGS][12];
    __shared__ double s_B[N_IMGS][9];
    __shared__ double s_rn[N_IMGS], s_rd[N_IMGS];

    if (blockIdx.x == 0) {
        // ---- F computation: one warp, lanes 0-15 -> n=0, 16-31 -> n=1 ----
        if (threadIdx.y != 0) return;
        int lane = threadIdx.x;
        int n = lane >> 4;
        int r = lane & 15;
        double p1[3][4], p2[3][4];
        #pragma unroll
        for (int i = 0; i < 3; i++)
            #pragma unroll
            for (int j = 0; j < 4; j++) {
                p1[i][j] = (double)P1g[n*12 + i*4 + j];
                p2[i][j] = (double)P2g[n*12 + i*4 + j];
            }
        // phase 1: null-vector cofactors (r<4) and G = P1 P1^T (r=4..12)
        if (r < 4) {
            double ca[3], cb[3], cc[3];
            int ja = (r == 0) ? 1 : 0;
            int jb = (r <= 1) ? 2 : 1;
            int jc = (r == 3) ? 2 : 3;
            #pragma unroll
            for (int i = 0; i < 3; i++) { ca[i]=p1[i][ja]; cb[i]=p1[i][jb]; cc[i]=p1[i][jc]; }
            double m = det3cols(ca, cb, cc);
            s_v[n][r] = (r & 1) ? -m : m;
        } else if (r < 13) {
            int idx = r - 4;
            int i = idx / 3, k = idx % 3;
            double s = 0.0;
            #pragma unroll
            for (int j = 0; j < 4; j++) s += p1[i][j]*p1[k][j];
            s_G[n][idx] = s;
        }
        __syncwarp();
        // phase 2: reciprocals (two independent long-latency ops in parallel)
        if (r == 0) {
            double n2 = s_v[n][0]*s_v[n][0] + s_v[n][1]*s_v[n][1]
                      + s_v[n][2]*s_v[n][2] + s_v[n][3]*s_v[n][3];
            s_rn[n] = 1.0 / sqrt(n2);
        } else if (r == 1) {
            const double* G = s_G[n];
            double detG = G[0]*(G[4]*G[8]-G[5]*G[7])
                        - G[1]*(G[3]*G[8]-G[5]*G[6])
                        + G[2]*(G[3]*G[7]-G[4]*G[6]);
            s_rd[n] = 1.0 / detG;
        }
        __syncwarp();
        // phase 3: e2 (r<3) and Gi = adj(G)/detG (r=3..11)
        if (r < 3) {
            double s = 0.0;
            #pragma unroll
            for (int j = 0; j < 4; j++) s += p2[r][j]*s_v[n][j];
            s_e2[n][r] = s * s_rn[n];
        } else if (r < 12) {
            int idx = r - 3;
            int i = idx / 3, j = idx % 3;
            const double* G = s_G[n];
            int r1 = (j == 0) ? 1 : 0, r2 = (j == 2) ? 1 : 2;
            int c1 = (i == 0) ? 1 : 0, c2 = (i == 2) ? 1 : 2;
            double m = G[r1*3+c1]*G[r2*3+c2] - G[r1*3+c2]*G[r2*3+c1];
            if ((i + j) & 1) m = -m;
            s_Gi[n][idx] = m * s_rd[n];
        }
        __syncwarp();
        // phase 4: pinv(P1) = P1^T Gi   (12 entries)
        if (r < 12) {
            int m_ = r / 3, j = r % 3;
            double s = 0.0;
            #pragma unroll
            for (int k = 0; k < 3; k++) s += p1[k][m_]*s_Gi[n][k*3+j];
            s_pinv[n][r] = s;
        }
        __syncwarp();
        // phase 5: B = P2 @ pinv   (9 entries)
        if (r < 9) {
            int i = r / 3, j = r % 3;
            double s = 0.0;
            #pragma unroll
            for (int m_ = 0; m_ < 4; m_++) s += p2[i][m_]*s_pinv[n][m_*3+j];
            s_B[n][r] = s;
        }
        __syncwarp();
        // phase 6: F = skew(e2) @ B
        if (r < 9) {
            int i = r / 3, j = r % 3;
            const double* e2 = s_e2[n];
            const double* B  = s_B[n];
            double F;
            if      (i == 0) F = -e2[2]*B[3+j] + e2[1]*B[6+j];
            else if (i == 1) F =  e2[2]*B[j]   - e2[0]*B[6+j];
            else             F = -e2[1]*B[j]   + e2[0]*B[3+j];
            g_F[n][r] = (float)F;
        }
        return;
    }

    // ---- transpose+convert path ----
    int b  = blockIdx.x - 1;                 // 0..2047
    int n  = b >> 10;                        // /1024
    int ct = ((b >> 7) & 7) * 32;            // channel tile
    int pt = (b & 127) * 32;                 // pixel tile
    int tx = threadIdx.x, ty = threadIdx.y;  // (32, 8)
    const float* src = feat2 + (size_t)n * C_CH * HWPIX;
    #pragma unroll
    for (int k = 0; k < 4; k++)
        tile[ty + 8*k][tx] = src[(ct + ty + 8*k) * HWPIX + pt + tx];   // [chan][pix]
    __syncthreads();
    __half* dst = (__half*)g_feat2h + (size_t)n * HWPIX * C_CH;
    int tid = ty * 32 + tx;
    int c2  = tid & 15;         // half2 index within 32 channels
    int pr  = tid >> 4;         // 0..15 pixel row
    #pragma unroll
    for (int k = 0; k < 2; k++) {
        int row = pr + 16*k;    // pixel within tile
        __half2 v = __floats2half2_rn(tile[2*c2][row], tile[2*c2+1][row]);
        ((__half2*)(dst + (size_t)(pt + row) * C_CH + ct))[c2] = v;
    }
}

// ---------------- fused locs + sampling + max-over-S kernel -----------------
// 1 warp = 1 pixel (all 256 channels), 8 warps/block.
__global__ __launch_bounds__(256) void sample_kernel(float* __restrict__ out) {
    __shared__ uint4 s_wgt[8][S_STEPS];   // 4 packed half2 weights per sample (8KB)
    __shared__ int4  s_off[8][S_STEPS];   // 4 corner uint4-indices (base)    (8KB)
    int lane = threadIdx.x;               // 0..31
    int wy   = threadIdx.y;               // 0..7 pixel-in-block
    int gp   = blockIdx.x * 8 + wy;
    int n    = gp >> 12;
    int p    = gp & 4095;

    // ---- phase A: epipolar line + per-sample weights/offsets (fp32) ----
    {
        float hf = (float)(p >> 6);
        float wf = (float)(p & 63);
        const float* F = g_F[n];
        float a = F[0]*wf + F[1]*hf + F[2];
        float b = F[3]*wf + F[4]*hf + F[5];
        float c = F[6]*wf + F[7]*hf + F[8];
        float sb = (b > 0.f) ? 1.f : ((b < 0.f) ? -1.f : 0.f);
        float sa = (a > 0.f) ? 1.f : ((a < 0.f) ? -1.f : 0.f);
        float db = sb * fmaxf(fabsf(b), EPSV);
        float da = sa * fmaxf(fabsf(a), EPSV);
        const float xmax = 63.f, ymax = 63.f;
        float by1 = -c / db;
        float by2 = -(xmax*a + c) / db;
        float bx0 = -c / da;
        float bx3 = -(ymax*b + c) / da;
        float px[4] = {bx0, 0.f, xmax, bx3};
        float py[4] = {0.f, by1, by2, ymax};
        bool m0 = (bx0 >= EPSV) && (bx0 <  xmax - EPSV);
        bool m1 = (by1 >  EPSV) && (by1 <= ymax - EPSV);
        bool m2 = (by2 >= EPSV) && (by2 <  ymax - EPSV);
        bool m3 = (bx3 >  EPSV) && (bx3 <= xmax - EPSV);
        int nint = (int)m0 + (int)m1 + (int)m2 + (int)m3;
        bool valid2 = nint >= 2;
        bool mm[4];
        if (valid2) { mm[0]=m0; mm[1]=m1; mm[2]=m2; mm[3]=m3; }
        else        { mm[0]=true; mm[1]=true; mm[2]=false; mm[3]=false; }
        int i0 = -1, i1 = -1;
        #pragma unroll
        for (int i = 0; i < 4; i++) {
            if (mm[i]) { if (i0 < 0) i0 = i; else if (i1 < 0) i1 = i; }
        }
        float sx, sy, vx, vy;
        if (valid2) { sx = px[i0]; sy = py[i0]; vx = px[i1]-px[i0]; vy = py[i1]-py[i0]; }
        else        { sx = -10000.f; sy = -10000.f; vx = 0.f; vy = 0.f; }

        int nb = n * HWPIX;
        #pragma unroll
        for (int t2 = 0; t2 < 2; t2++) {
            int s = lane + 32*t2;
            float t  = (float)s / 63.0f;
            float lx = sx + vx * t;
            float ly = sy + vy * t;
            float gx = lx / 63.0f * 2.0f - 1.0f;
            float gy = ly / 63.0f * 2.0f - 1.0f;
            float x  = (gx + 1.0f) * 32.0f - 0.5f;
            float y  = (gy + 1.0f) * 32.0f - 0.5f;
            float x0 = floorf(x), y0 = floorf(y);
            float wx1 = x - x0, wy1 = y - y0;
            bool vx0 = (x0        >= 0.f) && (x0        < 64.f);
            bool vx1 = (x0 + 1.f  >= 0.f) && (x0 + 1.f  < 64.f);
            bool vy0 = (y0        >= 0.f) && (y0        < 64.f);
            bool vy1 = (y0 + 1.f  >= 0.f) && (y0 + 1.f  < 64.f);
            float w0 = (vx0 && vy0) ? (1.f - wx1) * (1.f - wy1) : 0.f;
            float w1 = (vx1 && vy0) ? wx1 * (1.f - wy1)         : 0.f;
            float w2 = (vx0 && vy1) ? (1.f - wx1) * wy1         : 0.f;
            float w3 = (vx1 && vy1) ? wx1 * wy1                 : 0.f;
            unsigned u0 = (unsigned)__half_as_ushort(__float2half_rn(w0)) * 0x10001u;
            unsigned u1 = (unsigned)__half_as_ushort(__float2half_rn(w1)) * 0x10001u;
            unsigned u2 = (unsigned)__half_as_ushort(__float2half_rn(w2)) * 0x10001u;
            unsigned u3 = (unsigned)__half_as_ushort(__float2half_rn(w3)) * 0x10001u;
            int cx0 = (int)fminf(fmaxf(x0,       0.f), 63.f);
            int cx1 = (int)fminf(fmaxf(x0 + 1.f, 0.f), 63.f);
            int cy0 = (int)fminf(fmaxf(y0,       0.f), 63.f);
            int cy1 = (int)fminf(fmaxf(y0 + 1.f, 0.f), 63.f);
            int4 o;
            o.x = (nb + cy0*64 + cx0) * (C_CH/8);
            o.y = (nb + cy0*64 + cx1) * (C_CH/8);
            o.z = (nb + cy1*64 + cx0) * (C_CH/8);
            o.w = (nb + cy1*64 + cx1) * (C_CH/8);
            s_wgt[wy][s] = make_uint4(u0, u1, u2, u3);
            s_off[wy][s] = o;
        }
    }
    __syncwarp();

    // ---- phase B: sample loop, half2 interp + max ----
    const __half2 h2zero = __float2half2_rn(0.0f);
    __half2 a0 = __float2half2_rn(-65504.f);
    __half2 a1 = a0, a2 = a0, a3 = a0;
    const uint4* f = (const uint4*)g_feat2h;
    #pragma unroll 2
    for (int s = 0; s < S_STEPS; s++) {
        uint4 wp = s_wgt[wy][s];
        if ((wp.x | wp.y | wp.z | wp.w) == 0u) {
            a0 = __hmax2(a0, h2zero);
            a1 = __hmax2(a1, h2zero);
            a2 = __hmax2(a2, h2zero);
            a3 = __hmax2(a3, h2zero);
            continue;
        }
        int4 o = s_off[wy][s];
        uint4 r0 = f[o.x + lane];
        uint4 r1 = f[o.y + lane];
        uint4 r2 = f[o.z + lane];
        uint4 r3 = f[o.w + lane];
        __half2 w0 = *reinterpret_cast<__half2*>(&wp.x);
        __half2 w1 = *reinterpret_cast<__half2*>(&wp.y);
        __half2 w2 = *reinterpret_cast<__half2*>(&wp.z);
        __half2 w3 = *reinterpret_cast<__half2*>(&wp.w);
        const __half2* h0 = reinterpret_cast<const __half2*>(&r0);
        const __half2* h1 = reinterpret_cast<const __half2*>(&r1);
        const __half2* h2 = reinterpret_cast<const __half2*>(&r2);
        const __half2* h3 = reinterpret_cast<const __half2*>(&r3);
        __half2 v;
        v = __hmul2(w3, h3[0]); v = __hfma2(w2, h2[0], v); v = __hfma2(w1, h1[0], v); v = __hfma2(w0, h0[0], v);
        a0 = __hmax2(a0, v);
        v = __hmul2(w3, h3[1]); v = __hfma2(w2, h2[1], v); v = __hfma2(w1, h1[1], v); v = __hfma2(w0, h0[1], v);
        a1 = __hmax2(a1, v);
        v = __hmul2(w3, h3[2]); v = __hfma2(w2, h2[2], v); v = __hfma2(w1, h1[2], v); v = __hfma2(w0, h0[2], v);
        a2 = __hmax2(a2, v);
        v = __hmul2(w3, h3[3]); v = __hfma2(w2, h2[3], v); v = __hfma2(w1, h1[3], v); v = __hfma2(w0, h0[3], v);
        a3 = __hmax2(a3, v);
    }

    // ---- stage results into shared (reuse this warp's s_wgt row: 256 floats) ----
    {
        float* sOutW = (float*)&s_wgt[wy][0];
        float2 t;
        t = __half22float2(a0); sOutW[lane*8 + 0] = t.x; sOutW[lane*8 + 1] = t.y;
        t = __half22float2(a1); sOutW[lane*8 + 2] = t.x; sOutW[lane*8 + 3] = t.y;
        t = __half22float2(a2); sOutW[lane*8 + 4] = t.x; sOutW[lane*8 + 5] = t.y;
        t = __half22float2(a3); sOutW[lane*8 + 6] = t.x; sOutW[lane*8 + 7] = t.y;
    }
    __syncthreads();

    // ---- coalesced store: thread = channel, 8 pixels -> 2x STG.128 ----
    {
        int c   = wy * 32 + lane;          // 0..255
        const float* sOut = (const float*)&s_wgt[0][0];   // [pix*256 + c]
        int gpb = blockIdx.x * 8;
        int nB  = gpb >> 12;
        int pB  = gpb & 4095;
        float4 o1 = make_float4(sOut[0*256 + c], sOut[1*256 + c],
                                sOut[2*256 + c], sOut[3*256 + c]);
        float4 o2 = make_float4(sOut[4*256 + c], sOut[5*256 + c],
                                sOut[6*256 + c], sOut[7*256 + c]);
        size_t base = ((size_t)(nB * C_CH + c)) * HWPIX + pB;
        *reinterpret_cast<float4*>(out + base)     = o1;
        *reinterpret_cast<float4*>(out + base + 4) = o2;
    }
}

// ---------------- launch ------------------------------------------------------
extern "C" void kernel_launch(void* const* d_in, const int* in_sizes, int n_in,
                              void* d_out, int out_size) {
    (void)in_sizes; (void)n_in; (void)out_size;
    const float* feat2 = (const float*)d_in[1];
    const float* P1    = (const float*)d_in[2];
    const float* P2    = (const float*)d_in[3];

    prep_kernel<<<2049, dim3(32, 8)>>>(feat2, P1, P2);
    sample_kernel<<<NPIX / 8, dim3(32, 8)>>>((float*)d_out);
}